// round 1
// baseline (speedup 1.0000x reference)
#include <cuda_runtime.h>
#include <math.h>

#define BATCH 8
#define NSEQ  2048
#define CDIM  512

// Scratch (allocation-free rule: __device__ globals)
__device__ float g_q[BATCH * NSEQ * CDIM];
__device__ float g_k[BATCH * NSEQ * CDIM];
__device__ float g_v[BATCH * NSEQ * CDIM];
__device__ float g_s[(size_t)BATCH * NSEQ * NSEQ];

// ---------------------------------------------------------------------------
// QKV projection: out[r,d] = sum_c feat[r,c] * W[d,c] + b[d]
// M=16384, N=512, K=512 (NT gemm). blockIdx.z selects Q/K/V.
// ---------------------------------------------------------------------------
__global__ __launch_bounds__(256) void qkv_kernel(
    const float* __restrict__ feat,
    const float* __restrict__ wq, const float* __restrict__ bq,
    const float* __restrict__ wk, const float* __restrict__ bk,
    const float* __restrict__ wv, const float* __restrict__ bv)
{
    const float* W;
    const float* bias;
    float* out;
    if (blockIdx.z == 0)      { W = wq; bias = bq; out = g_q; }
    else if (blockIdx.z == 1) { W = wk; bias = bk; out = g_k; }
    else                      { W = wv; bias = bv; out = g_v; }

    __shared__ float As[16][128];
    __shared__ float Bs[16][128];

    const int tid = threadIdx.x;
    const int tx = tid & 15;
    const int ty = tid >> 4;
    const int rowBase = blockIdx.y * 128;
    const int colBase = blockIdx.x * 128;

    float acc[8][8] = {};

    for (int kt = 0; kt < CDIM; kt += 16) {
        #pragma unroll
        for (int i = 0; i < 2; i++) {
            int li = tid * 2 + i;            // 0..511
            int r  = li >> 2;                // row within tile
            int c4 = (li & 3) * 4;           // float offset within 16-wide k
            float4 a = *(const float4*)&feat[(size_t)(rowBase + r) * CDIM + kt + c4];
            As[c4 + 0][r] = a.x; As[c4 + 1][r] = a.y;
            As[c4 + 2][r] = a.z; As[c4 + 3][r] = a.w;
            float4 b = *(const float4*)&W[(size_t)(colBase + r) * CDIM + kt + c4];
            Bs[c4 + 0][r] = b.x; Bs[c4 + 1][r] = b.y;
            Bs[c4 + 2][r] = b.z; Bs[c4 + 3][r] = b.w;
        }
        __syncthreads();
        #pragma unroll
        for (int k = 0; k < 16; k++) {
            float ra[8], rb[8];
            #pragma unroll
            for (int i = 0; i < 8; i++) ra[i] = As[k][ty * 8 + i];
            #pragma unroll
            for (int j = 0; j < 8; j++) rb[j] = Bs[k][tx * 8 + j];
            #pragma unroll
            for (int i = 0; i < 8; i++)
                #pragma unroll
                for (int j = 0; j < 8; j++)
                    acc[i][j] = fmaf(ra[i], rb[j], acc[i][j]);
        }
        __syncthreads();
    }

    #pragma unroll
    for (int i = 0; i < 8; i++) {
        int r = rowBase + ty * 8 + i;
        #pragma unroll
        for (int j = 0; j < 8; j += 4) {
            int c = colBase + tx * 8 + j;
            float4 o;
            o.x = acc[i][j + 0] + bias[c + 0];
            o.y = acc[i][j + 1] + bias[c + 1];
            o.z = acc[i][j + 2] + bias[c + 2];
            o.w = acc[i][j + 3] + bias[c + 3];
            *(float4*)&out[(size_t)r * CDIM + c] = o;
        }
    }
}

// ---------------------------------------------------------------------------
// Scores: S[b,n,m] = sum_d Q[b,n,d] * K[b,m,d]   (NT gemm, per batch)
// M=N=2048, K=512
// ---------------------------------------------------------------------------
__global__ __launch_bounds__(256) void scores_kernel()
{
    const int b = blockIdx.z;
    const float* Aq = g_q + (size_t)b * NSEQ * CDIM;
    const float* Bk = g_k + (size_t)b * NSEQ * CDIM;
    float* out = g_s + (size_t)b * NSEQ * NSEQ;

    __shared__ float As[16][128];
    __shared__ float Bs[16][128];

    const int tid = threadIdx.x;
    const int tx = tid & 15;
    const int ty = tid >> 4;
    const int rowBase = blockIdx.y * 128;
    const int colBase = blockIdx.x * 128;

    float acc[8][8] = {};

    for (int kt = 0; kt < CDIM; kt += 16) {
        #pragma unroll
        for (int i = 0; i < 2; i++) {
            int li = tid * 2 + i;
            int r  = li >> 2;
            int c4 = (li & 3) * 4;
            float4 a = *(const float4*)&Aq[(size_t)(rowBase + r) * CDIM + kt + c4];
            As[c4 + 0][r] = a.x; As[c4 + 1][r] = a.y;
            As[c4 + 2][r] = a.z; As[c4 + 3][r] = a.w;
            float4 bb = *(const float4*)&Bk[(size_t)(colBase + r) * CDIM + kt + c4];
            Bs[c4 + 0][r] = bb.x; Bs[c4 + 1][r] = bb.y;
            Bs[c4 + 2][r] = bb.z; Bs[c4 + 3][r] = bb.w;
        }
        __syncthreads();
        #pragma unroll
        for (int k = 0; k < 16; k++) {
            float ra[8], rb[8];
            #pragma unroll
            for (int i = 0; i < 8; i++) ra[i] = As[k][ty * 8 + i];
            #pragma unroll
            for (int j = 0; j < 8; j++) rb[j] = Bs[k][tx * 8 + j];
            #pragma unroll
            for (int i = 0; i < 8; i++)
                #pragma unroll
                for (int j = 0; j < 8; j++)
                    acc[i][j] = fmaf(ra[i], rb[j], acc[i][j]);
        }
        __syncthreads();
    }

    #pragma unroll
    for (int i = 0; i < 8; i++) {
        int r = rowBase + ty * 8 + i;
        #pragma unroll
        for (int j = 0; j < 8; j += 4) {
            int c = colBase + tx * 8 + j;
            float4 o;
            o.x = acc[i][j + 0];
            o.y = acc[i][j + 1];
            o.z = acc[i][j + 2];
            o.w = acc[i][j + 3];
            *(float4*)&out[(size_t)r * NSEQ + c] = o;
        }
    }
}

// ---------------------------------------------------------------------------
// Row softmax over 2048 elements, then post-softmax scale by 1/sqrt(C).
// One block (256 threads) per row; 16384 rows.
// ---------------------------------------------------------------------------
__global__ __launch_bounds__(256) void softmax_kernel()
{
    float* s = g_s + (size_t)blockIdx.x * NSEQ;
    const int tid = threadIdx.x;
    const int lane = tid & 31;
    const int w = tid >> 5;
    __shared__ float sh[8];

    float vals[8];
    #pragma unroll
    for (int i = 0; i < 2; i++) {
        float4 x = *(const float4*)&s[tid * 8 + i * 4];
        vals[i * 4 + 0] = x.x; vals[i * 4 + 1] = x.y;
        vals[i * 4 + 2] = x.z; vals[i * 4 + 3] = x.w;
    }

    float lmax = vals[0];
    #pragma unroll
    for (int i = 1; i < 8; i++) lmax = fmaxf(lmax, vals[i]);
    #pragma unroll
    for (int o = 16; o > 0; o >>= 1)
        lmax = fmaxf(lmax, __shfl_xor_sync(0xffffffffu, lmax, o));
    if (lane == 0) sh[w] = lmax;
    __syncthreads();
    float m = sh[0];
    #pragma unroll
    for (int i = 1; i < 8; i++) m = fmaxf(m, sh[i]);

    float lsum = 0.f;
    #pragma unroll
    for (int i = 0; i < 8; i++) { vals[i] = __expf(vals[i] - m); lsum += vals[i]; }
    #pragma unroll
    for (int o = 16; o > 0; o >>= 1)
        lsum += __shfl_xor_sync(0xffffffffu, lsum, o);
    __syncthreads();
    if (lane == 0) sh[w] = lsum;
    __syncthreads();
    float tot = 0.f;
    #pragma unroll
    for (int i = 0; i < 8; i++) tot += sh[i];

    const float scale = 0.044194173824159216f / tot;  // (1/sqrt(512)) / sum

    #pragma unroll
    for (int i = 0; i < 2; i++) {
        float4 x;
        x.x = vals[i * 4 + 0] * scale;
        x.y = vals[i * 4 + 1] * scale;
        x.z = vals[i * 4 + 2] * scale;
        x.w = vals[i * 4 + 3] * scale;
        *(float4*)&s[tid * 8 + i * 4] = x;
    }
}

// ---------------------------------------------------------------------------
// PV: out[b,n,d] = feat[b,n,d] + sum_m attn[b,n,m] * V[b,m,d]
// M=2048, N=512, K=2048 (NN gemm, per batch), fused residual add.
// ---------------------------------------------------------------------------
__global__ __launch_bounds__(256) void pv_kernel(
    const float* __restrict__ feat, float* __restrict__ out)
{
    const int b = blockIdx.z;
    const float* Ap = g_s + (size_t)b * NSEQ * NSEQ;   // attn (post-softmax, scaled)
    const float* Bv = g_v + (size_t)b * NSEQ * CDIM;

    __shared__ float As[16][128];
    __shared__ float Bs[16][128];

    const int tid = threadIdx.x;
    const int tx = tid & 15;
    const int ty = tid >> 4;
    const int rowBase = blockIdx.y * 128;
    const int colBase = blockIdx.x * 128;

    float acc[8][8] = {};

    for (int kt = 0; kt < NSEQ; kt += 16) {
        #pragma unroll
        for (int i = 0; i < 2; i++) {
            int li = tid * 2 + i;
            // A tile [128 rows x 16 k] from attn (lda = NSEQ), stored transposed
            int r  = li >> 2;
            int c4 = (li & 3) * 4;
            float4 a = *(const float4*)&Ap[(size_t)(rowBase + r) * NSEQ + kt + c4];
            As[c4 + 0][r] = a.x; As[c4 + 1][r] = a.y;
            As[c4 + 2][r] = a.z; As[c4 + 3][r] = a.w;
            // B tile [16 k x 128 cols] from V (NN: k rows contiguous in d), direct
            int rb = li >> 5;                 // 0..15
            int cb = (li & 31) * 4;           // 0..124
            float4 bb = *(const float4*)&Bv[(size_t)(kt + rb) * CDIM + colBase + cb];
            *(float4*)&Bs[rb][cb] = bb;
        }
        __syncthreads();
        #pragma unroll
        for (int k = 0; k < 16; k++) {
            float ra[8], rv[8];
            #pragma unroll
            for (int i = 0; i < 8; i++) ra[i] = As[k][ty * 8 + i];
            #pragma unroll
            for (int j = 0; j < 8; j++) rv[j] = Bs[k][tx * 8 + j];
            #pragma unroll
            for (int i = 0; i < 8; i++)
                #pragma unroll
                for (int j = 0; j < 8; j++)
                    acc[i][j] = fmaf(ra[i], rv[j], acc[i][j]);
        }
        __syncthreads();
    }

    #pragma unroll
    for (int i = 0; i < 8; i++) {
        int r = rowBase + ty * 8 + i;                 // seq index within batch
        size_t rowOff = ((size_t)b * NSEQ + r) * CDIM;
        #pragma unroll
        for (int j = 0; j < 8; j += 4) {
            int c = colBase + tx * 8 + j;
            float4 f = *(const float4*)&feat[rowOff + c];
            float4 o;
            o.x = acc[i][j + 0] + f.x;
            o.y = acc[i][j + 1] + f.y;
            o.z = acc[i][j + 2] + f.z;
            o.w = acc[i][j + 3] + f.w;
            *(float4*)&out[rowOff + c] = o;
        }
    }
}

// ---------------------------------------------------------------------------
extern "C" void kernel_launch(void* const* d_in, const int* in_sizes, int n_in,
                              void* d_out, int out_size)
{
    const float* feat = (const float*)d_in[0];
    const float* wq   = (const float*)d_in[1];
    const float* bq   = (const float*)d_in[2];
    const float* wk   = (const float*)d_in[3];
    const float* bk   = (const float*)d_in[4];
    const float* wv   = (const float*)d_in[5];
    const float* bv   = (const float*)d_in[6];
    float* out = (float*)d_out;

    // QKV: N=512/128=4 col blocks, M=16384/128=128 row blocks, z = {q,k,v}
    qkv_kernel<<<dim3(4, 128, 3), 256>>>(feat, wq, bq, wk, bk, wv, bv);
    // Scores: 2048/128 = 16 x 16 blocks, 8 batches
    scores_kernel<<<dim3(16, 16, 8), 256>>>();
    // Softmax: one block per row
    softmax_kernel<<<dim3(BATCH * NSEQ), 256>>>();
    // PV + residual: 512/128 = 4 col blocks, 2048/128 = 16 row blocks, 8 batches
    pv_kernel<<<dim3(4, 16, 8), 256>>>(feat, out);
}

// round 3
// speedup vs baseline: 3.5740x; 3.5740x over previous
#include <cuda_runtime.h>
#include <cstdint>

#define BATCH 8
#define NSEQ  2048
#define CDIM  512

// ---------------------------------------------------------------------------
// Scratch (__device__ globals per allocation-free rule)
// ---------------------------------------------------------------------------
__device__ float g_q[BATCH * NSEQ * CDIM];
__device__ float g_k[BATCH * NSEQ * CDIM];
__device__ float g_v[BATCH * NSEQ * CDIM];
__device__ float g_s[(size_t)BATCH * NSEQ * NSEQ];

// ---------------------------------------------------------------------------
// Helpers
// ---------------------------------------------------------------------------
__device__ __forceinline__ uint32_t smem_to_u32(const void* p) {
    uint32_t a;
    asm("{ .reg .u64 t; cvta.to.shared.u64 t, %1; cvt.u32.u64 %0, t; }" : "=r"(a) : "l"(p));
    return a;
}

__device__ __forceinline__ void cp_async16(uint32_t saddr, const void* gptr) {
    asm volatile("cp.async.cg.shared.global [%0], [%1], 16;" :: "r"(saddr), "l"(gptr));
}
#define CP_COMMIT() asm volatile("cp.async.commit_group;" ::: "memory")
#define CP_WAIT0()  asm volatile("cp.async.wait_group 0;" ::: "memory")

// m16n8k8 tf32 MMA (baseline PTX feature, works on compute_103 target)
__device__ __forceinline__ void mma_tf32(float c[4],
                                         uint32_t a0, uint32_t a1, uint32_t a2, uint32_t a3,
                                         uint32_t b0, uint32_t b1) {
    asm volatile(
        "mma.sync.aligned.m16n8k8.row.col.f32.tf32.tf32.f32 "
        "{%0,%1,%2,%3}, {%4,%5,%6,%7}, {%8,%9}, {%0,%1,%2,%3};"
        : "+f"(c[0]), "+f"(c[1]), "+f"(c[2]), "+f"(c[3])
        : "r"(a0), "r"(a1), "r"(a2), "r"(a3), "r"(b0), "r"(b1));
}

// ---------------------------------------------------------------------------
// SMEM tile layouts (float offsets, padded to kill bank conflicts)
//   NT tile: 128 rows x 32 k-floats, row stride 36 -> 4608 floats / buffer
//   NN tile:  32 k-rows x 128 n-floats, row stride 136 -> 4352 floats / buffer
// ---------------------------------------------------------------------------
#define NT_STRIDE 36
#define NN_STRIDE 136
#define NT_FLOATS (128 * NT_STRIDE)   // 4608
#define NN_FLOATS (32 * NN_STRIDE)    // 4352

// Load 128x32 K-major tile (rows rowBase..+127, k = kt..kt+31) via cp.async
__device__ __forceinline__ void load_nt(const float* __restrict__ g, long ld,
                                        int rowBase, int kt, uint32_t sbase, int tid) {
    #pragma unroll
    for (int i = 0; i < 4; i++) {
        int idx = i * 256 + tid;       // 0..1023 float4s
        int r = idx >> 3;              // 0..127
        int f4 = idx & 7;              // 0..7
        cp_async16(sbase + (uint32_t)(r * NT_STRIDE + f4 * 4) * 4,
                   g + (long)(rowBase + r) * ld + kt + f4 * 4);
    }
}

// Load 32x128 N-major tile (k rows kt..kt+31, cols colBase..+127) via cp.async
__device__ __forceinline__ void load_nn(const float* __restrict__ g, long ld,
                                        int colBase, int kt, uint32_t sbase, int tid) {
    #pragma unroll
    for (int i = 0; i < 4; i++) {
        int idx = i * 256 + tid;
        int r = idx >> 5;              // 0..31
        int c4 = idx & 31;             // 0..31
        cp_async16(sbase + (uint32_t)(r * NN_STRIDE + c4 * 4) * 4,
                   g + (long)(kt + r) * ld + colBase + c4 * 4);
    }
}

// One 32-k slab of MMAs. A from NT tile; B from NT tile (b_nt=1) or NN tile.
// Warp tile 32x64 at (m0, n0). acc[2][8][4].
__device__ __forceinline__ void compute_slab(const float* __restrict__ As,
                                             const float* __restrict__ Bs,
                                             int b_nt, float acc[2][8][4],
                                             int m0, int n0, int lq, int lr) {
    #pragma unroll
    for (int kk = 0; kk < 4; kk++) {
        int k = kk * 8 + lr;
        uint32_t a[2][4];
        #pragma unroll
        for (int mt = 0; mt < 2; mt++) {
            const float* p = As + (m0 + mt * 16 + lq) * NT_STRIDE + k;
            a[mt][0] = __float_as_uint(p[0]);
            a[mt][1] = __float_as_uint(p[8 * NT_STRIDE]);
            a[mt][2] = __float_as_uint(p[4]);
            a[mt][3] = __float_as_uint(p[8 * NT_STRIDE + 4]);
        }
        uint32_t b[8][2];
        if (b_nt) {
            #pragma unroll
            for (int nt = 0; nt < 8; nt++) {
                const float* p = Bs + (n0 + nt * 8 + lq) * NT_STRIDE + k;
                b[nt][0] = __float_as_uint(p[0]);
                b[nt][1] = __float_as_uint(p[4]);
            }
        } else {
            #pragma unroll
            for (int nt = 0; nt < 8; nt++) {
                const float* p = Bs + k * NN_STRIDE + n0 + nt * 8 + lq;
                b[nt][0] = __float_as_uint(p[0]);
                b[nt][1] = __float_as_uint(p[4 * NN_STRIDE]);
            }
        }
        #pragma unroll
        for (int mt = 0; mt < 2; mt++)
            #pragma unroll
            for (int nt = 0; nt < 8; nt++)
                mma_tf32(acc[mt][nt], a[mt][0], a[mt][1], a[mt][2], a[mt][3],
                         b[nt][0], b[nt][1]);
    }
}

// ---------------------------------------------------------------------------
// Kernel 1: QKV projections (NT GEMM). out[r,d] = feat[r,:] . W[d,:] + b[d]
// M=16384, N=512, K=512. z selects Q/K/V.
// ---------------------------------------------------------------------------
__global__ __launch_bounds__(256) void qkv_mma(
    const float* __restrict__ feat,
    const float* __restrict__ wq, const float* __restrict__ bq,
    const float* __restrict__ wk, const float* __restrict__ bk,
    const float* __restrict__ wv, const float* __restrict__ bv)
{
    extern __shared__ float sm[];
    uint32_t sb = smem_to_u32(sm);
    const int tid = threadIdx.x;
    const int wid = tid >> 5, lane = tid & 31;
    const int lq = lane >> 2, lr = lane & 3;
    const int m0 = (wid >> 1) * 32, n0 = (wid & 1) * 64;
    const int z = blockIdx.z;
    const float* W    = (z == 0) ? wq : (z == 1) ? wk : wv;
    const float* bias = (z == 0) ? bq : (z == 1) ? bk : bv;
    float* out        = (z == 0) ? g_q : (z == 1) ? g_k : g_v;

    const int rowBase = blockIdx.y * 128;
    const int colBase = blockIdx.x * 128;

    // SMEM: A0 A1 B0 B1, each NT_FLOATS
    float* A[2] = { sm, sm + NT_FLOATS };
    float* B[2] = { sm + 2 * NT_FLOATS, sm + 3 * NT_FLOATS };
    uint32_t aAddr[2] = { sb, sb + NT_FLOATS * 4 };
    uint32_t bAddr[2] = { sb + 2 * NT_FLOATS * 4, sb + 3 * NT_FLOATS * 4 };

    float acc[2][8][4] = {};

    load_nt(feat, CDIM, rowBase, 0, aAddr[0], tid);
    load_nt(W,    CDIM, colBase, 0, bAddr[0], tid);
    CP_COMMIT(); CP_WAIT0();
    __syncthreads();

    const int nslab = CDIM / 32;
    for (int s = 0; s < nslab; s++) {
        int cur = s & 1;
        if (s + 1 < nslab) {
            int nxt = cur ^ 1;
            load_nt(feat, CDIM, rowBase, (s + 1) * 32, aAddr[nxt], tid);
            load_nt(W,    CDIM, colBase, (s + 1) * 32, bAddr[nxt], tid);
            CP_COMMIT();
        }
        compute_slab(A[cur], B[cur], 1, acc, m0, n0, lq, lr);
        if (s + 1 < nslab) CP_WAIT0();
        __syncthreads();
    }

    // Epilogue: add bias, store float2 per mma accumulator half
    #pragma unroll
    for (int mt = 0; mt < 2; mt++) {
        #pragma unroll
        for (int half = 0; half < 2; half++) {
            int row = rowBase + m0 + mt * 16 + lq + half * 8;
            #pragma unroll
            for (int nt = 0; nt < 8; nt++) {
                int col = colBase + n0 + nt * 8 + lr * 2;
                float2 o;
                o.x = acc[mt][nt][half * 2 + 0] + bias[col + 0];
                o.y = acc[mt][nt][half * 2 + 1] + bias[col + 1];
                *(float2*)&out[(long)row * CDIM + col] = o;
            }
        }
    }
}

// ---------------------------------------------------------------------------
// Kernel 2: scores (NT GEMM). S[b,n,m] = Q[b,n,:] . K[b,m,:]
// ---------------------------------------------------------------------------
__global__ __launch_bounds__(256) void scores_mma()
{
    extern __shared__ float sm[];
    uint32_t sb = smem_to_u32(sm);
    const int tid = threadIdx.x;
    const int wid = tid >> 5, lane = tid & 31;
    const int lq = lane >> 2, lr = lane & 3;
    const int m0 = (wid >> 1) * 32, n0 = (wid & 1) * 64;
    const int bz = blockIdx.z;

    const float* Aq = g_q + (long)bz * NSEQ * CDIM;
    const float* Bk = g_k + (long)bz * NSEQ * CDIM;
    float* out = g_s + (long)bz * NSEQ * NSEQ;
    const int rowBase = blockIdx.y * 128;
    const int colBase = blockIdx.x * 128;

    float* A[2] = { sm, sm + NT_FLOATS };
    float* B[2] = { sm + 2 * NT_FLOATS, sm + 3 * NT_FLOATS };
    uint32_t aAddr[2] = { sb, sb + NT_FLOATS * 4 };
    uint32_t bAddr[2] = { sb + 2 * NT_FLOATS * 4, sb + 3 * NT_FLOATS * 4 };

    float acc[2][8][4] = {};

    load_nt(Aq, CDIM, rowBase, 0, aAddr[0], tid);
    load_nt(Bk, CDIM, colBase, 0, bAddr[0], tid);
    CP_COMMIT(); CP_WAIT0();
    __syncthreads();

    const int nslab = CDIM / 32;
    for (int s = 0; s < nslab; s++) {
        int cur = s & 1;
        if (s + 1 < nslab) {
            int nxt = cur ^ 1;
            load_nt(Aq, CDIM, rowBase, (s + 1) * 32, aAddr[nxt], tid);
            load_nt(Bk, CDIM, colBase, (s + 1) * 32, bAddr[nxt], tid);
            CP_COMMIT();
        }
        compute_slab(A[cur], B[cur], 1, acc, m0, n0, lq, lr);
        if (s + 1 < nslab) CP_WAIT0();
        __syncthreads();
    }

    #pragma unroll
    for (int mt = 0; mt < 2; mt++) {
        #pragma unroll
        for (int half = 0; half < 2; half++) {
            int row = rowBase + m0 + mt * 16 + lq + half * 8;
            #pragma unroll
            for (int nt = 0; nt < 8; nt++) {
                int col = colBase + n0 + nt * 8 + lr * 2;
                float2 o;
                o.x = acc[mt][nt][half * 2 + 0];
                o.y = acc[mt][nt][half * 2 + 1];
                *(float2*)&out[(long)row * NSEQ + col] = o;
            }
        }
    }
}

// ---------------------------------------------------------------------------
// Kernel 3: row softmax over 2048, post-scale by 1/sqrt(C). One block per row.
// ---------------------------------------------------------------------------
__global__ __launch_bounds__(256) void softmax_kernel()
{
    float* s = g_s + (size_t)blockIdx.x * NSEQ;
    const int tid = threadIdx.x;
    const int lane = tid & 31;
    const int w = tid >> 5;
    __shared__ float sh[8];

    float vals[8];
    #pragma unroll
    for (int i = 0; i < 2; i++) {
        float4 x = *(const float4*)&s[tid * 8 + i * 4];
        vals[i * 4 + 0] = x.x; vals[i * 4 + 1] = x.y;
        vals[i * 4 + 2] = x.z; vals[i * 4 + 3] = x.w;
    }

    float lmax = vals[0];
    #pragma unroll
    for (int i = 1; i < 8; i++) lmax = fmaxf(lmax, vals[i]);
    #pragma unroll
    for (int o = 16; o > 0; o >>= 1)
        lmax = fmaxf(lmax, __shfl_xor_sync(0xffffffffu, lmax, o));
    if (lane == 0) sh[w] = lmax;
    __syncthreads();
    float m = sh[0];
    #pragma unroll
    for (int i = 1; i < 8; i++) m = fmaxf(m, sh[i]);

    float lsum = 0.f;
    #pragma unroll
    for (int i = 0; i < 8; i++) { vals[i] = __expf(vals[i] - m); lsum += vals[i]; }
    #pragma unroll
    for (int o = 16; o > 0; o >>= 1)
        lsum += __shfl_xor_sync(0xffffffffu, lsum, o);
    __syncthreads();
    if (lane == 0) sh[w] = lsum;
    __syncthreads();
    float tot = 0.f;
    #pragma unroll
    for (int i = 0; i < 8; i++) tot += sh[i];

    const float scale = 0.044194173824159216f / tot;  // (1/sqrt(512)) / sum

    #pragma unroll
    for (int i = 0; i < 2; i++) {
        float4 x;
        x.x = vals[i * 4 + 0] * scale;
        x.y = vals[i * 4 + 1] * scale;
        x.z = vals[i * 4 + 2] * scale;
        x.w = vals[i * 4 + 3] * scale;
        *(float4*)&s[tid * 8 + i * 4] = x;
    }
}

// ---------------------------------------------------------------------------
// Kernel 4: PV + residual (NN GEMM). out[b,n,d] = feat[b,n,d] + attn.V
// M=2048, N=512, K=2048 per batch.
// ---------------------------------------------------------------------------
__global__ __launch_bounds__(256) void pv_mma(const float* __restrict__ feat,
                                              float* __restrict__ out)
{
    extern __shared__ float sm[];
    uint32_t sb = smem_to_u32(sm);
    const int tid = threadIdx.x;
    const int wid = tid >> 5, lane = tid & 31;
    const int lq = lane >> 2, lr = lane & 3;
    const int m0 = (wid >> 1) * 32, n0 = (wid & 1) * 64;
    const int bz = blockIdx.z;

    const float* Ap = g_s + (long)bz * NSEQ * NSEQ;
    const float* Bv = g_v + (long)bz * NSEQ * CDIM;
    const int rowBase = blockIdx.y * 128;
    const int colBase = blockIdx.x * 128;

    float* A[2] = { sm, sm + NT_FLOATS };
    float* B[2] = { sm + 2 * NT_FLOATS, sm + 2 * NT_FLOATS + NN_FLOATS };
    uint32_t aAddr[2] = { sb, sb + NT_FLOATS * 4 };
    uint32_t bAddr[2] = { sb + 2 * NT_FLOATS * 4, sb + (2 * NT_FLOATS + NN_FLOATS) * 4 };

    float acc[2][8][4] = {};

    load_nt(Ap, NSEQ, rowBase, 0, aAddr[0], tid);
    load_nn(Bv, CDIM, colBase, 0, bAddr[0], tid);
    CP_COMMIT(); CP_WAIT0();
    __syncthreads();

    const int nslab = NSEQ / 32;
    for (int s = 0; s < nslab; s++) {
        int cur = s & 1;
        if (s + 1 < nslab) {
            int nxt = cur ^ 1;
            load_nt(Ap, NSEQ, rowBase, (s + 1) * 32, aAddr[nxt], tid);
            load_nn(Bv, CDIM, colBase, (s + 1) * 32, bAddr[nxt], tid);
            CP_COMMIT();
        }
        compute_slab(A[cur], B[cur], 0, acc, m0, n0, lq, lr);
        if (s + 1 < nslab) CP_WAIT0();
        __syncthreads();
    }

    #pragma unroll
    for (int mt = 0; mt < 2; mt++) {
        #pragma unroll
        for (int half = 0; half < 2; half++) {
            int row = rowBase + m0 + mt * 16 + lq + half * 8;   // seq idx in batch
            long gRow = (long)bz * NSEQ + row;
            #pragma unroll
            for (int nt = 0; nt < 8; nt++) {
                int col = colBase + n0 + nt * 8 + lr * 2;
                float2 f = *(const float2*)&feat[gRow * CDIM + col];
                float2 o;
                o.x = acc[mt][nt][half * 2 + 0] + f.x;
                o.y = acc[mt][nt][half * 2 + 1] + f.y;
                *(float2*)&out[gRow * CDIM + col] = o;
            }
        }
    }
}

// ---------------------------------------------------------------------------
#define SMEM_NT_BYTES (4 * NT_FLOATS * 4)                        // 73728
#define SMEM_PV_BYTES ((2 * NT_FLOATS + 2 * NN_FLOATS) * 4)      // 71680

extern "C" void kernel_launch(void* const* d_in, const int* in_sizes, int n_in,
                              void* d_out, int out_size)
{
    const float* feat = (const float*)d_in[0];
    const float* wq   = (const float*)d_in[1];
    const float* bq   = (const float*)d_in[2];
    const float* wk   = (const float*)d_in[3];
    const float* bk   = (const float*)d_in[4];
    const float* wv   = (const float*)d_in[5];
    const float* bv   = (const float*)d_in[6];
    float* out = (float*)d_out;

    static int configured = 0;
    if (!configured) {
        cudaFuncSetAttribute(qkv_mma,    cudaFuncAttributeMaxDynamicSharedMemorySize, SMEM_NT_BYTES);
        cudaFuncSetAttribute(scores_mma, cudaFuncAttributeMaxDynamicSharedMemorySize, SMEM_NT_BYTES);
        cudaFuncSetAttribute(pv_mma,     cudaFuncAttributeMaxDynamicSharedMemorySize, SMEM_PV_BYTES);
        configured = 1;
    }

    // QKV: 4 col blocks (512/128), 128 row blocks (16384/128), z = {q,k,v}
    qkv_mma<<<dim3(4, 128, 3), 256, SMEM_NT_BYTES>>>(feat, wq, bq, wk, bk, wv, bv);
    // Scores: 16x16 blocks (2048/128), 8 batches
    scores_mma<<<dim3(16, 16, 8), 256, SMEM_NT_BYTES>>>();
    // Softmax: one block per row
    softmax_kernel<<<dim3(BATCH * NSEQ), 256>>>();
    // PV + residual: 4 col blocks, 16 row blocks, 8 batches
    pv_mma<<<dim3(4, 16, 8), 256, SMEM_PV_BYTES>>>(feat, out);
}

// round 4
// speedup vs baseline: 8.3027x; 2.3231x over previous
#include <cuda_runtime.h>
#include <cuda_bf16.h>
#include <cstdint>

#define BATCH 8
#define NSEQ  2048
#define CDIM  512

// ---------------------------------------------------------------------------
// Scratch (__device__ globals per allocation-free rule), all bf16
// ---------------------------------------------------------------------------
__device__ __align__(16) __nv_bfloat16 g_fb[BATCH * NSEQ * CDIM];      // feat bf16
__device__ __align__(16) __nv_bfloat16 g_wb[3 * CDIM * CDIM];          // wq,wk,wv bf16
__device__ __align__(16) __nv_bfloat16 g_qb[BATCH * NSEQ * CDIM];
__device__ __align__(16) __nv_bfloat16 g_kb[BATCH * NSEQ * CDIM];
__device__ __align__(16) __nv_bfloat16 g_vb[BATCH * NSEQ * CDIM];      // natural [m][d]
__device__ __align__(16) __nv_bfloat16 g_s[(size_t)BATCH * NSEQ * NSEQ];

// ---------------------------------------------------------------------------
// Helpers
// ---------------------------------------------------------------------------
__device__ __forceinline__ uint32_t smem_to_u32(const void* p) {
    uint32_t a;
    asm("{ .reg .u64 t; cvta.to.shared.u64 t, %1; cvt.u32.u64 %0, t; }" : "=r"(a) : "l"(p));
    return a;
}

__device__ __forceinline__ void cp_async16(uint32_t saddr, const void* gptr) {
    asm volatile("cp.async.cg.shared.global [%0], [%1], 16;" :: "r"(saddr), "l"(gptr));
}
#define CP_COMMIT() asm volatile("cp.async.commit_group;" ::: "memory")
#define CP_WAIT0()  asm volatile("cp.async.wait_group 0;" ::: "memory")

__device__ __forceinline__ void ldsm4(uint32_t r[4], uint32_t addr) {
    asm volatile("ldmatrix.sync.aligned.m8n8.x4.shared.b16 {%0,%1,%2,%3}, [%4];"
        : "=r"(r[0]), "=r"(r[1]), "=r"(r[2]), "=r"(r[3]) : "r"(addr));
}
__device__ __forceinline__ void ldsm4t(uint32_t r[4], uint32_t addr) {
    asm volatile("ldmatrix.sync.aligned.m8n8.x4.trans.shared.b16 {%0,%1,%2,%3}, [%4];"
        : "=r"(r[0]), "=r"(r[1]), "=r"(r[2]), "=r"(r[3]) : "r"(addr));
}

__device__ __forceinline__ void mma_bf16(float c[4], const uint32_t a[4], const uint32_t b[2]) {
    asm volatile(
        "mma.sync.aligned.m16n8k16.row.col.f32.bf16.bf16.f32 "
        "{%0,%1,%2,%3}, {%4,%5,%6,%7}, {%8,%9}, {%0,%1,%2,%3};"
        : "+f"(c[0]), "+f"(c[1]), "+f"(c[2]), "+f"(c[3])
        : "r"(a[0]), "r"(a[1]), "r"(a[2]), "r"(a[3]), "r"(b[0]), "r"(b[1]));
}

__device__ __forceinline__ uint32_t packbf(float x, float y) {
    __nv_bfloat162 h = __floats2bfloat162_rn(x, y);
    return *reinterpret_cast<uint32_t*>(&h);
}
__device__ __forceinline__ float2 unpackbf(uint32_t u) {
    __nv_bfloat162 h = *reinterpret_cast<__nv_bfloat162*>(&u);
    return __bfloat1622float2(h);
}

// ---------------------------------------------------------------------------
// SMEM tile layouts (bf16, padded rows so ldmatrix 16B units hit distinct banks)
//   NT tile: 128 rows x 64 k-bf16, row stride 72 bf16 = 144 B -> 18432 B
//   NN tile:  64 k-rows x 128 n-bf16, row stride 136 bf16 = 272 B -> 17408 B
// ---------------------------------------------------------------------------
#define NT_TILE_B 18432
#define NN_TILE_B 17408

__device__ __forceinline__ void load_ntb(const __nv_bfloat16* __restrict__ g, long ld,
                                         int rowBase, int kt, uint32_t sbase, int tid) {
    #pragma unroll
    for (int i = 0; i < 4; i++) {
        int idx = i * 256 + tid;      // 1024 chunks of 16B
        int r = idx >> 3, f8 = idx & 7;
        cp_async16(sbase + (uint32_t)(r * 144 + f8 * 16),
                   g + (long)(rowBase + r) * ld + kt + f8 * 8);
    }
}

__device__ __forceinline__ void load_nnb(const __nv_bfloat16* __restrict__ g, long ld,
                                         int colBase, int kt, uint32_t sbase, int tid) {
    #pragma unroll
    for (int i = 0; i < 4; i++) {
        int idx = i * 256 + tid;
        int r = idx >> 4, c8 = idx & 15;
        cp_async16(sbase + (uint32_t)(r * 272 + c8 * 16),
                   g + (long)(kt + r) * ld + colBase + c8 * 8);
    }
}

// One 64-k slab. A from NT tile; B from NT tile (BNN=0) or NN tile w/ trans (BNN=1).
template<int BNN>
__device__ __forceinline__ void slab_bf16(uint32_t aBase, uint32_t bBase,
                                          float acc[2][8][4], int m0, int n0, int lane) {
    uint32_t aOff[2], bOff[4];
    #pragma unroll
    for (int mt = 0; mt < 2; mt++)
        aOff[mt] = (uint32_t)((m0 + mt * 16 + (lane & 15)) * 144 + ((lane & 16) ? 16 : 0));
    #pragma unroll
    for (int nt2 = 0; nt2 < 4; nt2++) {
        if (BNN)
            bOff[nt2] = (uint32_t)(((lane & 7) + ((lane & 8) ? 8 : 0)) * 272
                        + (n0 + nt2 * 16) * 2 + ((lane & 16) ? 16 : 0));
        else
            bOff[nt2] = (uint32_t)((n0 + nt2 * 16 + (lane & 7) + ((lane & 16) ? 8 : 0)) * 144
                        + ((lane & 8) ? 16 : 0));
    }
    #pragma unroll
    for (int kk = 0; kk < 4; kk++) {
        uint32_t a[2][4];
        ldsm4(a[0], aBase + aOff[0] + kk * 32);
        ldsm4(a[1], aBase + aOff[1] + kk * 32);
        uint32_t b[4][4];
        #pragma unroll
        for (int nt2 = 0; nt2 < 4; nt2++) {
            if (BNN) ldsm4t(b[nt2], bBase + bOff[nt2] + kk * 16 * 272);
            else     ldsm4 (b[nt2], bBase + bOff[nt2] + kk * 32);
        }
        #pragma unroll
        for (int mt = 0; mt < 2; mt++)
            #pragma unroll
            for (int nt2 = 0; nt2 < 4; nt2++) {
                mma_bf16(acc[mt][nt2 * 2 + 0], a[mt], &b[nt2][0]);
                mma_bf16(acc[mt][nt2 * 2 + 1], a[mt], &b[nt2][2]);
            }
    }
}

// ---------------------------------------------------------------------------
// Convert kernels (f32 -> bf16)
// ---------------------------------------------------------------------------
__global__ __launch_bounds__(256) void conv_feat(const float4* __restrict__ in) {
    int idx = blockIdx.x * 256 + threadIdx.x;        // 2,097,152 float4s
    float4 v = in[idx];
    uint2 o;
    o.x = packbf(v.x, v.y);
    o.y = packbf(v.z, v.w);
    ((uint2*)g_fb)[idx] = o;
}

__global__ __launch_bounds__(256) void conv_w(const float4* __restrict__ wq,
                                              const float4* __restrict__ wk,
                                              const float4* __restrict__ wv) {
    int idx = blockIdx.x * 256 + threadIdx.x;        // 65536 float4s per weight
    const float4* w = (blockIdx.y == 0) ? wq : (blockIdx.y == 1) ? wk : wv;
    float4 v = w[idx];
    uint2 o;
    o.x = packbf(v.x, v.y);
    o.y = packbf(v.z, v.w);
    ((uint2*)g_wb)[blockIdx.y * 65536 + idx] = o;
}

// ---------------------------------------------------------------------------
// Kernel 1: QKV projections (NT). out bf16. z selects Q/K/V. M=16384,N=512,K=512
// ---------------------------------------------------------------------------
__global__ __launch_bounds__(256, 2) void qkv_bf16(
    const float* __restrict__ bq, const float* __restrict__ bk,
    const float* __restrict__ bv)
{
    extern __shared__ char sm[];
    uint32_t sb = smem_to_u32(sm);
    const int tid = threadIdx.x;
    const int wid = tid >> 5, lane = tid & 31;
    const int lq = lane >> 2, lr = lane & 3;
    const int m0 = (wid >> 1) * 32, n0 = (wid & 1) * 64;
    const int z = blockIdx.z;
    const __nv_bfloat16* W = g_wb + (long)z * CDIM * CDIM;
    const float* bias = (z == 0) ? bq : (z == 1) ? bk : bv;
    __nv_bfloat16* out = (z == 0) ? g_qb : (z == 1) ? g_kb : g_vb;

    const int rowBase = blockIdx.y * 128;
    const int colBase = blockIdx.x * 128;

    uint32_t aAddr[2] = { sb, sb + NT_TILE_B };
    uint32_t bAddr[2] = { sb + 2 * NT_TILE_B, sb + 3 * NT_TILE_B };

    float acc[2][8][4] = {};

    load_ntb(g_fb, CDIM, rowBase, 0, aAddr[0], tid);
    load_ntb(W,    CDIM, colBase, 0, bAddr[0], tid);
    CP_COMMIT(); CP_WAIT0();
    __syncthreads();

    const int nslab = CDIM / 64;
    for (int s = 0; s < nslab; s++) {
        int cur = s & 1;
        if (s + 1 < nslab) {
            int nxt = cur ^ 1;
            load_ntb(g_fb, CDIM, rowBase, (s + 1) * 64, aAddr[nxt], tid);
            load_ntb(W,    CDIM, colBase, (s + 1) * 64, bAddr[nxt], tid);
            CP_COMMIT();
        }
        slab_bf16<0>(aAddr[cur], bAddr[cur], acc, m0, n0, lane);
        if (s + 1 < nslab) CP_WAIT0();
        __syncthreads();
    }

    #pragma unroll
    for (int mt = 0; mt < 2; mt++)
        #pragma unroll
        for (int half = 0; half < 2; half++) {
            int row = rowBase + m0 + mt * 16 + lq + half * 8;
            #pragma unroll
            for (int nt = 0; nt < 8; nt++) {
                int col = colBase + n0 + nt * 8 + lr * 2;
                uint32_t p = packbf(acc[mt][nt][half * 2 + 0] + bias[col + 0],
                                    acc[mt][nt][half * 2 + 1] + bias[col + 1]);
                *(uint32_t*)&out[(long)row * CDIM + col] = p;
            }
        }
}

// ---------------------------------------------------------------------------
// Kernel 2: scores (NT). S[b,n,m] = Q[b,n,:].K[b,m,:], bf16 out. K=512
// ---------------------------------------------------------------------------
__global__ __launch_bounds__(256, 2) void scores_bf16()
{
    extern __shared__ char sm[];
    uint32_t sb = smem_to_u32(sm);
    const int tid = threadIdx.x;
    const int wid = tid >> 5, lane = tid & 31;
    const int lq = lane >> 2, lr = lane & 3;
    const int m0 = (wid >> 1) * 32, n0 = (wid & 1) * 64;
    const int bz = blockIdx.z;

    const __nv_bfloat16* Aq = g_qb + (long)bz * NSEQ * CDIM;
    const __nv_bfloat16* Bk = g_kb + (long)bz * NSEQ * CDIM;
    __nv_bfloat16* out = g_s + (size_t)bz * NSEQ * NSEQ;
    const int rowBase = blockIdx.y * 128;
    const int colBase = blockIdx.x * 128;

    uint32_t aAddr[2] = { sb, sb + NT_TILE_B };
    uint32_t bAddr[2] = { sb + 2 * NT_TILE_B, sb + 3 * NT_TILE_B };

    float acc[2][8][4] = {};

    load_ntb(Aq, CDIM, rowBase, 0, aAddr[0], tid);
    load_ntb(Bk, CDIM, colBase, 0, bAddr[0], tid);
    CP_COMMIT(); CP_WAIT0();
    __syncthreads();

    const int nslab = CDIM / 64;
    for (int s = 0; s < nslab; s++) {
        int cur = s & 1;
        if (s + 1 < nslab) {
            int nxt = cur ^ 1;
            load_ntb(Aq, CDIM, rowBase, (s + 1) * 64, aAddr[nxt], tid);
            load_ntb(Bk, CDIM, colBase, (s + 1) * 64, bAddr[nxt], tid);
            CP_COMMIT();
        }
        slab_bf16<0>(aAddr[cur], bAddr[cur], acc, m0, n0, lane);
        if (s + 1 < nslab) CP_WAIT0();
        __syncthreads();
    }

    #pragma unroll
    for (int mt = 0; mt < 2; mt++)
        #pragma unroll
        for (int half = 0; half < 2; half++) {
            int row = rowBase + m0 + mt * 16 + lq + half * 8;
            #pragma unroll
            for (int nt = 0; nt < 8; nt++) {
                int col = colBase + n0 + nt * 8 + lr * 2;
                uint32_t p = packbf(acc[mt][nt][half * 2 + 0],
                                    acc[mt][nt][half * 2 + 1]);
                *(uint32_t*)&out[(size_t)row * NSEQ + col] = p;
            }
        }
}

// ---------------------------------------------------------------------------
// Kernel 3: row softmax over 2048 bf16, post-scale 1/sqrt(C). f32 math.
// ---------------------------------------------------------------------------
__global__ __launch_bounds__(256) void softmax_bf16()
{
    __nv_bfloat16* s = g_s + (size_t)blockIdx.x * NSEQ;
    const int tid = threadIdx.x;
    const int lane = tid & 31;
    const int w = tid >> 5;
    __shared__ float sh[8];

    uint4 raw = ((const uint4*)s)[tid];
    float2 p0 = unpackbf(raw.x), p1 = unpackbf(raw.y);
    float2 p2 = unpackbf(raw.z), p3 = unpackbf(raw.w);
    float vals[8] = { p0.x, p0.y, p1.x, p1.y, p2.x, p2.y, p3.x, p3.y };

    float lmax = vals[0];
    #pragma unroll
    for (int i = 1; i < 8; i++) lmax = fmaxf(lmax, vals[i]);
    #pragma unroll
    for (int o = 16; o > 0; o >>= 1)
        lmax = fmaxf(lmax, __shfl_xor_sync(0xffffffffu, lmax, o));
    if (lane == 0) sh[w] = lmax;
    __syncthreads();
    float m = sh[0];
    #pragma unroll
    for (int i = 1; i < 8; i++) m = fmaxf(m, sh[i]);

    float lsum = 0.f;
    #pragma unroll
    for (int i = 0; i < 8; i++) { vals[i] = __expf(vals[i] - m); lsum += vals[i]; }
    #pragma unroll
    for (int o = 16; o > 0; o >>= 1)
        lsum += __shfl_xor_sync(0xffffffffu, lsum, o);
    __syncthreads();
    if (lane == 0) sh[w] = lsum;
    __syncthreads();
    float tot = 0.f;
    #pragma unroll
    for (int i = 0; i < 8; i++) tot += sh[i];

    const float scale = 0.044194173824159216f / tot;  // (1/sqrt(512)) / sum

    uint4 o;
    o.x = packbf(vals[0] * scale, vals[1] * scale);
    o.y = packbf(vals[2] * scale, vals[3] * scale);
    o.z = packbf(vals[4] * scale, vals[5] * scale);
    o.w = packbf(vals[6] * scale, vals[7] * scale);
    ((uint4*)s)[tid] = o;
}

// ---------------------------------------------------------------------------
// Kernel 4: PV + residual. A = attn (NT, K=m), B = V natural [m][d] (NN, trans
// ldmatrix). out f32. M=2048, N=512, K=2048 per batch.
// ---------------------------------------------------------------------------
__global__ __launch_bounds__(256, 2) void pv_bf16(const float* __restrict__ feat,
                                                  float* __restrict__ out)
{
    extern __shared__ char sm[];
    uint32_t sb = smem_to_u32(sm);
    const int tid = threadIdx.x;
    const int wid = tid >> 5, lane = tid & 31;
    const int lq = lane >> 2, lr = lane & 3;
    const int m0 = (wid >> 1) * 32, n0 = (wid & 1) * 64;
    const int bz = blockIdx.z;

    const __nv_bfloat16* Ap = g_s + (size_t)bz * NSEQ * NSEQ;
    const __nv_bfloat16* Bv = g_vb + (long)bz * NSEQ * CDIM;
    const int rowBase = blockIdx.y * 128;
    const int colBase = blockIdx.x * 128;

    uint32_t aAddr[2] = { sb, sb + NT_TILE_B };
    uint32_t bAddr[2] = { sb + 2 * NT_TILE_B, sb + 2 * NT_TILE_B + NN_TILE_B };

    float acc[2][8][4] = {};

    load_ntb(Ap, NSEQ, rowBase, 0, aAddr[0], tid);
    load_nnb(Bv, CDIM, colBase, 0, bAddr[0], tid);
    CP_COMMIT(); CP_WAIT0();
    __syncthreads();

    const int nslab = NSEQ / 64;
    for (int s = 0; s < nslab; s++) {
        int cur = s & 1;
        if (s + 1 < nslab) {
            int nxt = cur ^ 1;
            load_ntb(Ap, NSEQ, rowBase, (s + 1) * 64, aAddr[nxt], tid);
            load_nnb(Bv, CDIM, colBase, (s + 1) * 64, bAddr[nxt], tid);
            CP_COMMIT();
        }
        slab_bf16<1>(aAddr[cur], bAddr[cur], acc, m0, n0, lane);
        if (s + 1 < nslab) CP_WAIT0();
        __syncthreads();
    }

    #pragma unroll
    for (int mt = 0; mt < 2; mt++)
        #pragma unroll
        for (int half = 0; half < 2; half++) {
            int row = rowBase + m0 + mt * 16 + lq + half * 8;
            long gRow = (long)bz * NSEQ + row;
            #pragma unroll
            for (int nt = 0; nt < 8; nt++) {
                int col = colBase + n0 + nt * 8 + lr * 2;
                float2 f = *(const float2*)&feat[gRow * CDIM + col];
                float2 o;
                o.x = acc[mt][nt][half * 2 + 0] + f.x;
                o.y = acc[mt][nt][half * 2 + 1] + f.y;
                *(float2*)&out[gRow * CDIM + col] = o;
            }
        }
}

// ---------------------------------------------------------------------------
#define SMEM_NT_BYTES (4 * NT_TILE_B)                 // 73728
#define SMEM_PV_BYTES (2 * NT_TILE_B + 2 * NN_TILE_B) // 71680

extern "C" void kernel_launch(void* const* d_in, const int* in_sizes, int n_in,
                              void* d_out, int out_size)
{
    const float* feat = (const float*)d_in[0];
    const float* wq   = (const float*)d_in[1];
    const float* bq   = (const float*)d_in[2];
    const float* wk   = (const float*)d_in[3];
    const float* bk   = (const float*)d_in[4];
    const float* wv   = (const float*)d_in[5];
    const float* bv   = (const float*)d_in[6];
    float* out = (float*)d_out;

    static int configured = 0;
    if (!configured) {
        cudaFuncSetAttribute(qkv_bf16,    cudaFuncAttributeMaxDynamicSharedMemorySize, SMEM_NT_BYTES);
        cudaFuncSetAttribute(scores_bf16, cudaFuncAttributeMaxDynamicSharedMemorySize, SMEM_NT_BYTES);
        cudaFuncSetAttribute(pv_bf16,     cudaFuncAttributeMaxDynamicSharedMemorySize, SMEM_PV_BYTES);
        configured = 1;
    }

    // Convert inputs to bf16
    conv_feat<<<dim3(8192), 256>>>((const float4*)feat);
    conv_w<<<dim3(256, 3), 256>>>((const float4*)wq, (const float4*)wk, (const float4*)wv);

    // QKV: 4 col blocks (512/128), 128 row blocks (16384/128), z = {q,k,v}
    qkv_bf16<<<dim3(4, 128, 3), 256, SMEM_NT_BYTES>>>(bq, bk, bv);
    // Scores: 16x16 blocks (2048/128), 8 batches
    scores_bf16<<<dim3(16, 16, 8), 256, SMEM_NT_BYTES>>>();
    // Softmax: one block per row
    softmax_bf16<<<dim3(BATCH * NSEQ), 256>>>();
    // PV + residual: 4 col blocks, 16 row blocks, 8 batches
    pv_bf16<<<dim3(4, 16, 8), 256, SMEM_PV_BYTES>>>(feat, out);
}